// round 1
// baseline (speedup 1.0000x reference)
#include <cuda_runtime.h>
#include <math.h>

#define B_   4096
#define IN_  512
#define OUT_ 512
#define NC_  64

// Scratch (no device allocation allowed -> __device__ globals)
__device__ float g_csumT[NC_ * OUT_];   // [n][o] : sum_i (mean + eps*std)
__device__ float g_rbf[B_ * NC_];       // [b][n]
__device__ float g_klpart[OUT_];        // per-o KL partial sums

// ---------------------------------------------------------------------------
// Kernel 1: fused reduction over the three (IN, OUT, NC) tensors.
// One block per o (512 blocks, 256 threads). Thread t handles n = t&63,
// i = (t>>6) + 4*j. Produces c_sumT[n][o] and g_klpart[o]. Deterministic.
// ---------------------------------------------------------------------------
__global__ void __launch_bounds__(256) reduce_coeff_kernel(
    const float* __restrict__ cm,
    const float* __restrict__ clv,
    const float* __restrict__ ep)
{
    const int o = blockIdx.x;
    const int t = threadIdx.x;
    const int n = t & 63;
    const int isub = t >> 6;
    const int stride = OUT_ * NC_;           // 32768 floats per i
    const size_t base = (size_t)o * NC_ + n;

    float acc_c = 0.f, acc_kl = 0.f;
    #pragma unroll 4
    for (int i = isub; i < IN_; i += 4) {
        size_t idx = base + (size_t)i * stride;
        float m  = cm[idx];
        float lv = clv[idx];
        float e  = ep[idx];
        float s  = expf(0.5f * lv);          // std
        acc_c  += m + e * s;
        acc_kl += s * s + m * m - 1.0f - lv; // var + mean^2 - 1 - logvar
    }

    __shared__ float sc[256];
    __shared__ float sk[256];
    sc[t] = acc_c;
    sk[t] = acc_kl;
    __syncthreads();

    if (t < 128) sk[t] += sk[t + 128];
    __syncthreads();
    if (t < 64) {
        sk[t] += sk[t + 64];
        // c_sum for this (o, n): sum the 4 i-subgroups
        g_csumT[(size_t)n * OUT_ + o] = sc[t] + sc[t + 64] + sc[t + 128] + sc[t + 192];
    }
    __syncthreads();
    if (t < 32) {
        float v = sk[t] + sk[t + 32];
        #pragma unroll
        for (int off = 16; off > 0; off >>= 1)
            v += __shfl_down_sync(0xffffffffu, v, off);
        if (t == 0) g_klpart[o] = v;
    }
}

// ---------------------------------------------------------------------------
// Kernel 2: RBF basis. Block handles 32 rows of x over all 64 centers.
// 256 threads: thread computes 8 (b,n) distance cells (bi = t>>3, n = (t&7)*8+j).
// ---------------------------------------------------------------------------
__global__ void __launch_bounds__(256) rbf_kernel(
    const float* __restrict__ x,
    const float* __restrict__ centers,
    const float* __restrict__ log_sigma)
{
    __shared__ float xs[32][36];   // pitch 36: float4-aligned, bank-staggered
    __shared__ float cs[64][36];

    const int t  = threadIdx.x;
    const int bb = blockIdx.x * 32;
    const int bi = t >> 3;      // 0..31
    const int ng = t & 7;       // 0..7 -> n = ng*8+j

    float acc[8];
    #pragma unroll
    for (int j = 0; j < 8; j++) acc[j] = 0.f;

    for (int kc = 0; kc < 16; kc++) {
        // x tile: 32 rows x 32 cols, one float4 per thread
        {
            int r = t >> 3;           // 0..31
            int c = (t & 7) * 4;      // 0..28
            float4 v = *(const float4*)&x[(size_t)(bb + r) * IN_ + kc * 32 + c];
            xs[r][c] = v.x; xs[r][c + 1] = v.y; xs[r][c + 2] = v.z; xs[r][c + 3] = v.w;
        }
        // centers tile: 64 rows x 32 cols, two float4 per thread
        {
            int r = t >> 2;           // 0..63
            int c = (t & 3) * 8;      // 0,8,16,24
            const float* src = &centers[(size_t)r * IN_ + kc * 32 + c];
            float4 v0 = *(const float4*)(src);
            float4 v1 = *(const float4*)(src + 4);
            cs[r][c]     = v0.x; cs[r][c + 1] = v0.y; cs[r][c + 2] = v0.z; cs[r][c + 3] = v0.w;
            cs[r][c + 4] = v1.x; cs[r][c + 5] = v1.y; cs[r][c + 6] = v1.z; cs[r][c + 7] = v1.w;
        }
        __syncthreads();

        #pragma unroll
        for (int ii = 0; ii < 32; ii++) {
            float xv = xs[bi][ii];
            #pragma unroll
            for (int j = 0; j < 8; j++) {
                float d = xv - cs[ng * 8 + j][ii];
                acc[j] += d * d;
            }
        }
        __syncthreads();
    }

    #pragma unroll
    for (int j = 0; j < 8; j++) {
        int n = ng * 8 + j;
        float s = expf(log_sigma[n]);
        float r = expf(-acc[j] / (2.0f * s * s + 1e-8f));
        g_rbf[(size_t)(bb + bi) * NC_ + n] = r;
    }
}

// ---------------------------------------------------------------------------
// Kernel 3: augmented GEMM. out[b][o] = sum_{k<512} x[b][k] W[k][o]
//                                     + sum_{k<64}  rbf[b][k] c_sumT[k][o]
// K = 576, boundary at k=512 is BK-aligned. 128x128x8 tile, 8x8 per thread,
// register prefetch of the next K-slab.
// ---------------------------------------------------------------------------
#define BM 128
#define BN 128
#define BK 8
#define KT_TOT 72   // 576 / 8; first 64 slabs from x/W, last 8 from rbf/c_sumT

__global__ void __launch_bounds__(256) gemm_kernel(
    const float* __restrict__ x,
    const float* __restrict__ W,
    float* __restrict__ out)
{
    __shared__ float As[BK][132];   // [k][m], pitch 132 (float4-aligned, staggered)
    __shared__ float Bs[BK][BN];    // [k][n]

    const int t  = threadIdx.x;
    const int bm = blockIdx.y * BM;
    const int bn = blockIdx.x * BN;
    const int tx = t & 15;          // 16 cols of threads
    const int ty = t >> 4;          // 16 rows of threads

    // load mappings
    const int arow = t >> 1;        // 0..127
    const int acol = (t & 1) * 4;   // 0 or 4
    const int brow = t >> 5;        // 0..7
    const int bcol = (t & 31) * 4;  // 0..124

    float acc[8][8];
    #pragma unroll
    for (int i = 0; i < 8; i++)
        #pragma unroll
        for (int j = 0; j < 8; j++) acc[i][j] = 0.f;

    // prefetch slab 0
    float4 av = *(const float4*)&x[(size_t)(bm + arow) * IN_ + acol];
    float4 bv = *(const float4*)&W[(size_t)brow * OUT_ + bn + bcol];

    for (int kt = 0; kt < KT_TOT; kt++) {
        As[acol][arow]     = av.x;
        As[acol + 1][arow] = av.y;
        As[acol + 2][arow] = av.z;
        As[acol + 3][arow] = av.w;
        *(float4*)&Bs[brow][bcol] = bv;
        __syncthreads();

        // prefetch slab kt+1
        int ktn = kt + 1;
        if (ktn < KT_TOT) {
            if (ktn < 64) {
                av = *(const float4*)&x[(size_t)(bm + arow) * IN_ + ktn * BK + acol];
                bv = *(const float4*)&W[(size_t)(ktn * BK + brow) * OUT_ + bn + bcol];
            } else {
                av = *(const float4*)&g_rbf[(size_t)(bm + arow) * NC_ + (ktn - 64) * BK + acol];
                bv = *(const float4*)&g_csumT[(size_t)((ktn - 64) * BK + brow) * OUT_ + bn + bcol];
            }
        }

        #pragma unroll
        for (int k = 0; k < BK; k++) {
            float a[8], b[8];
            *(float4*)&a[0] = *(const float4*)&As[k][ty * 8];
            *(float4*)&a[4] = *(const float4*)&As[k][ty * 8 + 4];
            *(float4*)&b[0] = *(const float4*)&Bs[k][tx * 8];
            *(float4*)&b[4] = *(const float4*)&Bs[k][tx * 8 + 4];
            #pragma unroll
            for (int i = 0; i < 8; i++)
                #pragma unroll
                for (int j = 0; j < 8; j++)
                    acc[i][j] += a[i] * b[j];
        }
        __syncthreads();
    }

    #pragma unroll
    for (int i = 0; i < 8; i++) {
        size_t row = (size_t)(bm + ty * 8 + i);
        #pragma unroll
        for (int j4 = 0; j4 < 8; j4 += 4) {
            float4 v = make_float4(acc[i][j4], acc[i][j4 + 1], acc[i][j4 + 2], acc[i][j4 + 3]);
            *(float4*)&out[row * OUT_ + bn + tx * 8 + j4] = v;
        }
    }
}

// ---------------------------------------------------------------------------
// Kernel 4: deterministic final KL reduce -> d_out[out_size-1]
// ---------------------------------------------------------------------------
__global__ void kl_final_kernel(float* __restrict__ out, int out_size)
{
    __shared__ float s[512];
    int t = threadIdx.x;
    s[t] = g_klpart[t];
    __syncthreads();
    #pragma unroll
    for (int off = 256; off > 0; off >>= 1) {
        if (t < off) s[t] += s[t + off];
        __syncthreads();
    }
    if (t == 0) out[out_size - 1] = 0.5f * s[0];
}

// ---------------------------------------------------------------------------
extern "C" void kernel_launch(void* const* d_in, const int* in_sizes, int n_in,
                              void* d_out, int out_size)
{
    const float* x         = (const float*)d_in[0];
    const float* centers   = (const float*)d_in[1];
    const float* log_sigma = (const float*)d_in[2];
    const float* cm        = (const float*)d_in[3];
    const float* clv       = (const float*)d_in[4];
    const float* W         = (const float*)d_in[5];
    const float* ep        = (const float*)d_in[6];
    float* out = (float*)d_out;

    reduce_coeff_kernel<<<512, 256>>>(cm, clv, ep);      // c_sumT + KL partials
    rbf_kernel<<<128, 256>>>(x, centers, log_sigma);     // rbf basis
    kl_final_kernel<<<1, 512>>>(out, out_size);          // KL scalar
    gemm_kernel<<<dim3(OUT_ / BN, B_ / BM), 256>>>(x, W, out);  // main output
}

// round 4
// speedup vs baseline: 2.4937x; 2.4937x over previous
#include <cuda_runtime.h>
#include <cuda_bf16.h>
#include <math.h>
#include <stdint.h>

#define B_    4096
#define IN_   512
#define OUT_  512
#define NC_   64
#define KTOT  1728   // 3 segments of 576: [x_hi|rbf_hi][x_hi|rbf_hi][x_lo|rbf_lo]
#define NCHK  54     // 1728 / 32

// ---------------- scratch (__device__ globals; no allocation allowed) -------
__device__ __nv_bfloat16 g_A[B_ * KTOT];     // A rows (b), K-major
__device__ __nv_bfloat16 g_Bm[OUT_ * KTOT];  // B rows (o), K-major
__device__ float g_klpart[OUT_];
__device__ float g_cn2[NC_];
__device__ float g_inv[NC_];

// ---------------------------------------------------------------------------
// convert_x: x -> bf16 hi/lo into g_A segments [0,512), [576,1088), [1152,1664)
// ---------------------------------------------------------------------------
__global__ void __launch_bounds__(256) convert_x_kernel(const float* __restrict__ x)
{
    int gid = blockIdx.x * 256 + threadIdx.x;
    int b   = gid >> 7;
    int col = (gid & 127) * 4;
    float4 v = *(const float4*)&x[(size_t)b * IN_ + col];

    __nv_bfloat16 h0 = __float2bfloat16(v.x), h1 = __float2bfloat16(v.y);
    __nv_bfloat16 h2 = __float2bfloat16(v.z), h3 = __float2bfloat16(v.w);
    __nv_bfloat16 l0 = __float2bfloat16(v.x - __bfloat162float(h0));
    __nv_bfloat16 l1 = __float2bfloat16(v.y - __bfloat162float(h1));
    __nv_bfloat16 l2 = __float2bfloat16(v.z - __bfloat162float(h2));
    __nv_bfloat16 l3 = __float2bfloat16(v.w - __bfloat162float(h3));

    __nv_bfloat162 hA = __nv_bfloat162(h0, h1), hB = __nv_bfloat162(h2, h3);
    __nv_bfloat162 lA = __nv_bfloat162(l0, l1), lB = __nv_bfloat162(l2, l3);
    uint2 hv = make_uint2(*(uint32_t*)&hA, *(uint32_t*)&hB);
    uint2 lv = make_uint2(*(uint32_t*)&lA, *(uint32_t*)&lB);

    size_t base = (size_t)b * KTOT + col;
    *(uint2*)&g_A[base]        = hv;
    *(uint2*)&g_A[base + 576]  = hv;
    *(uint2*)&g_A[base + 1152] = lv;
}

// ---------------------------------------------------------------------------
// convert_w: transpose W[k][o] -> g_Bm row o, hi/lo split.
// hi -> [0,512) and [1152,1664); lo -> [576,1088)
// ---------------------------------------------------------------------------
__global__ void __launch_bounds__(256) convert_w_kernel(const float* __restrict__ W)
{
    __shared__ float tile[32][33];
    int tx = threadIdx.x & 31, ty = threadIdx.x >> 5;     // 32 x 8
    int bx = blockIdx.x, by = blockIdx.y;

    #pragma unroll
    for (int i = 0; i < 4; i++)
        tile[ty + i * 8][tx] = W[(size_t)(by * 32 + ty + i * 8) * OUT_ + bx * 32 + tx];
    __syncthreads();

    #pragma unroll
    for (int i = 0; i < 4; i++) {
        int o = bx * 32 + ty + i * 8;
        int k = by * 32 + tx;
        float v = tile[tx][ty + i * 8];
        __nv_bfloat16 h = __float2bfloat16(v);
        __nv_bfloat16 l = __float2bfloat16(v - __bfloat162float(h));
        size_t base = (size_t)o * KTOT;
        g_Bm[base + k]        = h;
        g_Bm[base + 1152 + k] = h;
        g_Bm[base + 576 + k]  = l;
    }
}

// ---------------------------------------------------------------------------
// cn2: |c_n|^2 and 1/(2 sigma_n^2 + 1e-8)
// ---------------------------------------------------------------------------
__global__ void __launch_bounds__(128) cn2_kernel(const float* __restrict__ centers,
                                                  const float* __restrict__ log_sigma)
{
    int n = blockIdx.x, t = threadIdx.x;
    float s = 0.f;
    for (int k = t; k < IN_; k += 128) {
        float v = centers[(size_t)n * IN_ + k];
        s += v * v;
    }
    __shared__ float sh[128];
    sh[t] = s; __syncthreads();
    if (t < 64) sh[t] += sh[t + 64]; __syncthreads();
    if (t < 32) {
        float v = sh[t] + sh[t + 32];
        #pragma unroll
        for (int off = 16; off > 0; off >>= 1) v += __shfl_down_sync(0xffffffffu, v, off);
        if (t == 0) {
            g_cn2[n] = v;
            float sg = __expf(log_sigma[n]);
            g_inv[n] = 1.0f / (2.0f * sg * sg + 1e-8f);
        }
    }
}

// ---------------------------------------------------------------------------
// reduce_coeff: c_sum[o][n] = sum_i (mean + eps*std) + KL partials per o.
// Writes hi/lo bf16 into g_Bm segments [512,576),[1664,1728) hi, [1088,1152) lo.
// ---------------------------------------------------------------------------
__global__ void __launch_bounds__(256) reduce_coeff_kernel(
    const float* __restrict__ cm, const float* __restrict__ clv,
    const float* __restrict__ ep)
{
    const int o = blockIdx.x, t = threadIdx.x;
    const int n4 = t & 15, isub = t >> 4;
    const float4* cm4  = (const float4*)cm;
    const float4* clv4 = (const float4*)clv;
    const float4* ep4  = (const float4*)ep;

    float4 ac = make_float4(0.f, 0.f, 0.f, 0.f);
    float akl = 0.f;
    #pragma unroll 2
    for (int i = isub; i < IN_; i += 16) {
        size_t idx = (size_t)i * 8192 + o * 16 + n4;   // float4 index
        float4 m = cm4[idx], lv = clv4[idx], e = ep4[idx];
        float s0 = __expf(0.5f * lv.x), s1 = __expf(0.5f * lv.y);
        float s2 = __expf(0.5f * lv.z), s3 = __expf(0.5f * lv.w);
        ac.x += m.x + e.x * s0;  ac.y += m.y + e.y * s1;
        ac.z += m.z + e.z * s2;  ac.w += m.w + e.w * s3;
        akl += (s0*s0 + m.x*m.x - 1.f - lv.x) + (s1*s1 + m.y*m.y - 1.f - lv.y)
             + (s2*s2 + m.z*m.z - 1.f - lv.z) + (s3*s3 + m.w*m.w - 1.f - lv.w);
    }

    __shared__ float4 sc[16][16];   // [isub][n4]
    __shared__ float  sk[256];
    sc[isub][n4] = ac;
    sk[t] = akl;
    __syncthreads();

    if (t < 64) {
        float sum = 0.f;
        #pragma unroll
        for (int s2i = 0; s2i < 16; s2i++)
            sum += ((const float*)&sc[s2i][0])[t];
        __nv_bfloat16 h = __float2bfloat16(sum);
        __nv_bfloat16 l = __float2bfloat16(sum - __bfloat162float(h));
        size_t base = (size_t)o * KTOT;
        g_Bm[base + 512 + t]  = h;
        g_Bm[base + 1664 + t] = h;
        g_Bm[base + 1088 + t] = l;
    }
    if (t < 128) sk[t] += sk[t + 128];
    __syncthreads();
    if (t < 64) sk[t] += sk[t + 64];
    __syncthreads();
    if (t < 32) {
        float v = sk[t] + sk[t + 32];
        #pragma unroll
        for (int off = 16; off > 0; off >>= 1) v += __shfl_down_sync(0xffffffffu, v, off);
        if (t == 0) g_klpart[o] = v;
    }
}

// ---------------------------------------------------------------------------
// rbf_gemm: dot = x.c via conflict-free SIMT GEMM; rbf = exp(-(|x|^2-2dot+|c|^2)*inv)
// Writes hi/lo bf16 into g_A segments [512,576),[1088,1152) hi, [1664,1728) lo.
// ---------------------------------------------------------------------------
__global__ void __launch_bounds__(256) rbf_gemm_kernel(const float* __restrict__ x,
                                                       const float* __restrict__ centers)
{
    __shared__ float As[32][33];   // [k][row]
    __shared__ float Cs[32][68];   // [k][n]
    const int t = threadIdx.x;
    const int bm = blockIdx.x * 32;
    const int tx = t & 15, ty = t >> 4;

    float acc[2][4] = {{0.f,0.f,0.f,0.f},{0.f,0.f,0.f,0.f}};
    float sq0 = 0.f, sq1 = 0.f;

    for (int kt = 0; kt < 16; kt++) {
        {   int row = t >> 3, kq = (t & 7) * 4;
            float4 v = *(const float4*)&x[(size_t)(bm + row) * IN_ + kt * 32 + kq];
            As[kq][row] = v.x; As[kq+1][row] = v.y; As[kq+2][row] = v.z; As[kq+3][row] = v.w;
        }
        {   int n = t >> 2, kq = (t & 3) * 8;
            const float* src = &centers[(size_t)n * IN_ + kt * 32 + kq];
            float4 v0 = *(const float4*)src;
            float4 v1 = *(const float4*)(src + 4);
            Cs[kq  ][n] = v0.x; Cs[kq+1][n] = v0.y; Cs[kq+2][n] = v0.z; Cs[kq+3][n] = v0.w;
            Cs[kq+4][n] = v1.x; Cs[kq+5][n] = v1.y; Cs[kq+6][n] = v1.z; Cs[kq+7][n] = v1.w;
        }
        __syncthreads();
        #pragma unroll
        for (int k = 0; k < 32; k++) {
            float a0 = As[k][ty * 2], a1 = As[k][ty * 2 + 1];
            float4 c = *(const float4*)&Cs[k][tx * 4];
            acc[0][0] += a0 * c.x; acc[0][1] += a0 * c.y;
            acc[0][2] += a0 * c.z; acc[0][3] += a0 * c.w;
            acc[1][0] += a1 * c.x; acc[1][1] += a1 * c.y;
            acc[1][2] += a1 * c.z; acc[1][3] += a1 * c.w;
            sq0 += a0 * a0; sq1 += a1 * a1;
        }
        __syncthreads();
    }

    #pragma unroll
    for (int i = 0; i < 2; i++) {
        float sq = i ? sq1 : sq0;
        size_t base = (size_t)(bm + ty * 2 + i) * KTOT;
        #pragma unroll
        for (int j = 0; j < 4; j++) {
            int n = tx * 4 + j;
            float d2 = sq - 2.f * acc[i][j] + g_cn2[n];
            float r = __expf(-d2 * g_inv[n]);
            __nv_bfloat16 h = __float2bfloat16(r);
            __nv_bfloat16 l = __float2bfloat16(r - __bfloat162float(h));
            g_A[base + 512 + n]  = h;
            g_A[base + 1088 + n] = h;
            g_A[base + 1664 + n] = l;
        }
    }
}

// ---------------------------------------------------------------------------
// KL final reduce -> out[out_size-1]
// ---------------------------------------------------------------------------
__global__ void kl_final_kernel(float* __restrict__ out, int out_size)
{
    __shared__ float s[512];
    int t = threadIdx.x;
    s[t] = g_klpart[t];
    __syncthreads();
    #pragma unroll
    for (int off = 256; off > 0; off >>= 1) {
        if (t < off) s[t] += s[t + off];
        __syncthreads();
    }
    if (t == 0) out[out_size - 1] = 0.5f * s[0];
}

// ---------------------------------------------------------------------------
// mma.sync GEMM: out[4096x512] = g_A[4096x1728] @ g_Bm[512x1728]^T
// bf16 in, fp32 acc. 128x128x32 CTA tile, 8 warps (2x4), warp tile 64x32.
// cp.async 2-deep pipeline, XOR-swizzled smem, ldmatrix fragments.
// ---------------------------------------------------------------------------
__device__ __forceinline__ uint32_t smem_u32(const void* p) {
    uint32_t a;
    asm("{ .reg .u64 t; cvta.to.shared.u64 t, %1; cvt.u32.u64 %0, t; }" : "=r"(a) : "l"(p));
    return a;
}

#define LOAD_CHUNK(c, sbase) do {                                               \
    const __nv_bfloat16* pa = gA + (size_t)(c) * 32;                            \
    const __nv_bfloat16* pb = gB + (size_t)(c) * 32;                            \
    _Pragma("unroll")                                                           \
    for (int j = 0; j < 2; j++) {                                               \
        int q = half2_ + j;                                                     \
        uint32_t da = (sbase) + ldrow * 64 + (uint32_t)((q ^ swz) << 4);        \
        asm volatile("cp.async.cg.shared.global [%0], [%1], 16;"                \
                     :: "r"(da), "l"(pa + q * 8) : "memory");                   \
        asm volatile("cp.async.cg.shared.global [%0], [%1], 16;"                \
                     :: "r"(da + 8192), "l"(pb + q * 8) : "memory");            \
    }                                                                           \
} while (0)

__global__ void __launch_bounds__(256) gemm_mma_kernel(float* __restrict__ out)
{
    __shared__ __align__(1024) char smtc[2][16384];   // per buf: A [0,8K), B [8K,16K)
    const int t = threadIdx.x, lane = t & 31, wid = t >> 5;
    const int wm = wid & 1, wn = wid >> 1;            // warp grid: 2(M) x 4(N)
    const int bm = blockIdx.y * 128, bn = blockIdx.x * 128;

    const uint32_t s0 = smem_u32(&smtc[0][0]);
    const uint32_t s1 = smem_u32(&smtc[1][0]);

    // cp.async mapping: thread -> (row, 32B half)
    const int ldrow = t >> 1;
    const int half2_ = (t & 1) * 2;
    const int swz = (ldrow >> 1) & 3;
    const __nv_bfloat16* gA = g_A  + (size_t)(bm + ldrow) * KTOT;
    const __nv_bfloat16* gB = g_Bm + (size_t)(bn + ldrow) * KTOT;

    // ldmatrix per-lane geometry
    const int a_row = (lane & 7) | (lane & 8);        // row-in-16 for A x4
    const int a_kq  = lane >> 4;                      // 0/1: +8 elements
    const int b_row = (lane & 7) | ((lane >> 4) << 3);
    const int b_kq  = (lane >> 3) & 1;

    float acc[4][4][4];
    #pragma unroll
    for (int mt = 0; mt < 4; mt++)
        #pragma unroll
        for (int nt = 0; nt < 4; nt++)
            #pragma unroll
            for (int r = 0; r < 4; r++) acc[mt][nt][r] = 0.f;

    LOAD_CHUNK(0, s0);
    asm volatile("cp.async.commit_group;" ::: "memory");
    LOAD_CHUNK(1, s1);
    asm volatile("cp.async.commit_group;" ::: "memory");

    #pragma unroll 1
    for (int c = 0; c < NCHK; c++) {
        asm volatile("cp.async.wait_group 1;" ::: "memory");
        __syncthreads();
        const uint32_t sb = (c & 1) ? s1 : s0;

        #pragma unroll
        for (int kk = 0; kk < 2; kk++) {
            uint32_t a[4][4], b[2][4];
            #pragma unroll
            for (int mt = 0; mt < 4; mt++) {
                int row = wm * 64 + mt * 16 + a_row;
                uint32_t ad = sb + row * 64 +
                              (uint32_t)((((kk << 1) | a_kq) ^ ((row >> 1) & 3)) << 4);
                asm volatile(
                    "ldmatrix.sync.aligned.m8n8.x4.shared.b16 {%0,%1,%2,%3}, [%4];"
                    : "=r"(a[mt][0]), "=r"(a[mt][1]), "=r"(a[mt][2]), "=r"(a[mt][3])
                    : "r"(ad));
            }
            #pragma unroll
            for (int np = 0; np < 2; np++) {
                int row = wn * 32 + np * 16 + b_row;
                uint32_t bd = sb + 8192 + row * 64 +
                              (uint32_t)((((kk << 1) | b_kq) ^ ((row >> 1) & 3)) << 4);
                asm volatile(
                    "ldmatrix.sync.aligned.m8n8.x4.shared.b16 {%0,%1,%2,%3}, [%4];"
                    : "=r"(b[np][0]), "=r"(b[np][1]), "=r"(b[np][2]), "=r"(b[np][3])
                    : "r"(bd));
            }
            #pragma unroll
            for (int mt = 0; mt < 4; mt++)
                #pragma unroll
                for (int nt = 0; nt < 4; nt++)
                    asm volatile(
                        "mma.sync.aligned.m16n8k16.row.col.f32.bf16.bf16.f32 "
                        "{%0,%1,%2,%3}, {%4,%5,%6,%7}, {%8,%9}, {%0,%1,%2,%3};"
                        : "+f"(acc[mt][nt][0]), "+f"(acc[mt][nt][1]),
                          "+f"(acc[mt][nt][2]), "+f"(acc[mt][nt][3])
                        : "r"(a[mt][0]), "r"(a[mt][1]), "r"(a[mt][2]), "r"(a[mt][3]),
                          "r"(b[nt >> 1][(nt & 1) * 2]), "r"(b[nt >> 1][(nt & 1) * 2 + 1]));
        }

        __syncthreads();
        if (c + 2 < NCHK) {
            LOAD_CHUNK(c + 2, (c & 1) ? s1 : s0);
        }
        asm volatile("cp.async.commit_group;" ::: "memory");
    }

    // epilogue
    const int er = lane >> 2, ec = (lane & 3) * 2;
    #pragma unroll
    for (int mt = 0; mt < 4; mt++) {
        int r0 = bm + wm * 64 + mt * 16 + er;
        #pragma unroll
        for (int nt = 0; nt < 4; nt++) {
            int col = bn + wn * 32 + nt * 8 + ec;
            *(float2*)&out[(size_t)r0 * OUT_ + col] =
                make_float2(acc[mt][nt][0], acc[mt][nt][1]);
            *(float2*)&out[(size_t)(r0 + 8) * OUT_ + col] =
                make_float2(acc[mt][nt][2], acc[mt][nt][3]);
        }
    }
}

// ---------------------------------------------------------------------------
extern "C" void kernel_launch(void* const* d_in, const int* in_sizes, int n_in,
                              void* d_out, int out_size)
{
    const float* x         = (const float*)d_in[0];
    const float* centers   = (const float*)d_in[1];
    const float* log_sigma = (const float*)d_in[2];
    const float* cm        = (const float*)d_in[3];
    const float* clv       = (const float*)d_in[4];
    const float* W         = (const float*)d_in[5];
    const float* ep        = (const float*)d_in[6];
    float* out = (float*)d_out;

    convert_x_kernel<<<2048, 256>>>(x);
    convert_w_kernel<<<dim3(16, 16), 256>>>(W);
    cn2_kernel<<<64, 128>>>(centers, log_sigma);
    reduce_coeff_kernel<<<512, 256>>>(cm, clv, ep);
    rbf_gemm_kernel<<<128, 256>>>(x, centers);
    kl_final_kernel<<<1, 512>>>(out, out_size);
    gemm_mma_kernel<<<dim3(OUT_ / 128, B_ / 128), 256>>>(out);
}

// round 5
// speedup vs baseline: 3.2093x; 1.2869x over previous
#include <cuda_runtime.h>
#include <math.h>
#include <stdint.h>

#define B_   4096
#define IN_  512
#define OUT_ 512
#define NC_  64
#define KA   576     // 512 (x|W) + 64 (rbf|c_sum)
#define NCH  18      // 576 / 32

// ---------------- scratch (__device__ globals; no allocation allowed) -------
__device__ __align__(16) float g_Ax[B_ * IN_];     // tf32-RN rounded x
__device__ __align__(16) float g_Arbf[B_ * NC_];   // tf32-RN rounded rbf
__device__ __align__(16) float g_Bt[OUT_ * KA];    // row o: [W^T | c_sumT], rounded
__device__ float g_klpart[OUT_];

__device__ __forceinline__ float rna_tf32(float v) {
    uint32_t u;
    asm("cvt.rna.tf32.f32 %0, %1;" : "=r"(u) : "f"(v));
    return __uint_as_float(u);
}
__device__ __forceinline__ uint32_t smem_u32(const void* p) {
    uint32_t a;
    asm("{ .reg .u64 t; cvta.to.shared.u64 t, %1; cvt.u32.u64 %0, t; }" : "=r"(a) : "l"(p));
    return a;
}

// ---------------------------------------------------------------------------
// convert_w: transpose W[k][o] -> g_Bt[o][k], tf32-RN rounded.
// ---------------------------------------------------------------------------
__global__ void __launch_bounds__(256) convert_w_kernel(const float* __restrict__ W)
{
    __shared__ float tile[32][33];
    int tx = threadIdx.x & 31, ty = threadIdx.x >> 5;
    int bx = blockIdx.x, by = blockIdx.y;

    #pragma unroll
    for (int i = 0; i < 4; i++)
        tile[ty + i * 8][tx] = W[(size_t)(by * 32 + ty + i * 8) * OUT_ + bx * 32 + tx];
    __syncthreads();

    #pragma unroll
    for (int i = 0; i < 4; i++) {
        int o = bx * 32 + ty + i * 8;
        int k = by * 32 + tx;
        g_Bt[(size_t)o * KA + k] = rna_tf32(tile[tx][ty + i * 8]);
    }
}

// ---------------------------------------------------------------------------
// reduce_coeff: c_sum[o][n] = sum_i (mean + eps*std) + KL partials per o.
// DRAM-bound (201 MB). Writes rounded c_sumT into g_Bt[o][512+n].
// ---------------------------------------------------------------------------
__global__ void __launch_bounds__(256) reduce_coeff_kernel(
    const float* __restrict__ cm, const float* __restrict__ clv,
    const float* __restrict__ ep)
{
    const int o = blockIdx.x, t = threadIdx.x;
    const int n4 = t & 15, isub = t >> 4;
    const float4* cm4  = (const float4*)cm;
    const float4* clv4 = (const float4*)clv;
    const float4* ep4  = (const float4*)ep;

    float4 ac = make_float4(0.f, 0.f, 0.f, 0.f);
    float akl = 0.f;
    #pragma unroll 4
    for (int i = isub; i < IN_; i += 16) {
        size_t idx = (size_t)i * 8192 + o * 16 + n4;   // float4 index
        float4 m  = __ldcs(cm4 + idx);
        float4 lv = __ldcs(clv4 + idx);
        float4 e  = __ldcs(ep4 + idx);
        float s0 = __expf(0.5f * lv.x), s1 = __expf(0.5f * lv.y);
        float s2 = __expf(0.5f * lv.z), s3 = __expf(0.5f * lv.w);
        ac.x += m.x + e.x * s0;  ac.y += m.y + e.y * s1;
        ac.z += m.z + e.z * s2;  ac.w += m.w + e.w * s3;
        akl += (s0*s0 + m.x*m.x - 1.f - lv.x) + (s1*s1 + m.y*m.y - 1.f - lv.y)
             + (s2*s2 + m.z*m.z - 1.f - lv.z) + (s3*s3 + m.w*m.w - 1.f - lv.w);
    }

    __shared__ float4 sc[16][16];   // [isub][n4]
    __shared__ float  sk[256];
    sc[isub][n4] = ac;
    sk[t] = akl;
    __syncthreads();

    if (t < 64) {
        float sum = 0.f;
        #pragma unroll
        for (int s2i = 0; s2i < 16; s2i++)
            sum += ((const float*)&sc[s2i][0])[t];
        g_Bt[(size_t)o * KA + 512 + t] = rna_tf32(sum);
    }
    if (t < 128) sk[t] += sk[t + 128];
    __syncthreads();
    if (t < 64) sk[t] += sk[t + 64];
    __syncthreads();
    if (t < 32) {
        float v = sk[t] + sk[t + 32];
        #pragma unroll
        for (int off = 16; off > 0; off >>= 1) v += __shfl_down_sync(0xffffffffu, v, off);
        if (t == 0) g_klpart[o] = v;
    }
}

// ---------------------------------------------------------------------------
// rbf_fused: dot = x.c SIMT GEMM; also fuses |c|^2 (from tiles already loaded),
// sigma, and the tf32 rounding passthrough of x -> g_Ax (each x tile is read
// exactly once across blocks). rbf -> g_Arbf rounded.
// ---------------------------------------------------------------------------
__global__ void __launch_bounds__(256) rbf_fused_kernel(
    const float* __restrict__ x, const float* __restrict__ centers,
    const float* __restrict__ log_sigma)
{
    __shared__ float As[32][33];   // [k][row]
    __shared__ float Cs[32][68];   // [k][n]
    const int t = threadIdx.x;
    const int bm = blockIdx.x * 32;
    const int tx = t & 15, ty = t >> 4;

    float acc[2][4] = {{0.f,0.f,0.f,0.f},{0.f,0.f,0.f,0.f}};
    float sq0 = 0.f, sq1 = 0.f;
    float c2[4] = {0.f, 0.f, 0.f, 0.f};

    for (int kt = 0; kt < 16; kt++) {
        {   int row = t >> 3, kq = (t & 7) * 4;
            float4 v = *(const float4*)&x[(size_t)(bm + row) * IN_ + kt * 32 + kq];
            As[kq][row] = v.x; As[kq+1][row] = v.y; As[kq+2][row] = v.z; As[kq+3][row] = v.w;
            // tf32-RN rounded passthrough for the GEMM A matrix
            float4 rv = make_float4(rna_tf32(v.x), rna_tf32(v.y),
                                    rna_tf32(v.z), rna_tf32(v.w));
            *(float4*)&g_Ax[(size_t)(bm + row) * IN_ + kt * 32 + kq] = rv;
        }
        {   int n = t >> 2, kq = (t & 3) * 8;
            const float* src = &centers[(size_t)n * IN_ + kt * 32 + kq];
            float4 v0 = *(const float4*)src;
            float4 v1 = *(const float4*)(src + 4);
            Cs[kq  ][n] = v0.x; Cs[kq+1][n] = v0.y; Cs[kq+2][n] = v0.z; Cs[kq+3][n] = v0.w;
            Cs[kq+4][n] = v1.x; Cs[kq+5][n] = v1.y; Cs[kq+6][n] = v1.z; Cs[kq+7][n] = v1.w;
        }
        __syncthreads();
        #pragma unroll
        for (int k = 0; k < 32; k++) {
            float a0 = As[k][ty * 2], a1 = As[k][ty * 2 + 1];
            float4 c = *(const float4*)&Cs[k][tx * 4];
            acc[0][0] += a0 * c.x; acc[0][1] += a0 * c.y;
            acc[0][2] += a0 * c.z; acc[0][3] += a0 * c.w;
            acc[1][0] += a1 * c.x; acc[1][1] += a1 * c.y;
            acc[1][2] += a1 * c.z; acc[1][3] += a1 * c.w;
            sq0 += a0 * a0; sq1 += a1 * a1;
            c2[0] += c.x * c.x; c2[1] += c.y * c.y;
            c2[2] += c.z * c.z; c2[3] += c.w * c.w;
        }
        __syncthreads();
    }

    float inv[4];
    #pragma unroll
    for (int j = 0; j < 4; j++) {
        float sg = __expf(log_sigma[tx * 4 + j]);
        inv[j] = 1.0f / (2.0f * sg * sg + 1e-8f);
    }
    #pragma unroll
    for (int i = 0; i < 2; i++) {
        float sq = i ? sq1 : sq0;
        size_t base = (size_t)(bm + ty * 2 + i) * NC_;
        #pragma unroll
        for (int j = 0; j < 4; j++) {
            float d2 = sq - 2.f * acc[i][j] + c2[j];
            g_Arbf[base + tx * 4 + j] = rna_tf32(__expf(-d2 * inv[j]));
        }
    }
}

// ---------------------------------------------------------------------------
// tf32 mma GEMM: out[4096x512] = [g_Ax | g_Arbf] @ g_Bt^T, K = 576.
// 128x128x32 CTA tile, 8 warps (2x4), warp tile 64x32, cp.async 2-stage,
// XOR-swizzled fp32 smem, ldmatrix-b16 fragment loads (8x8 b16 == 8x4 fp32).
// Fused final KL reduce in block (0,0).
// ---------------------------------------------------------------------------
#define LOADC(c, stg) do {                                                    \
    const float* pa = ((c) < 16)                                              \
        ? g_Ax + (size_t)(bm + lrow) * IN_ + (c) * 32                         \
        : g_Arbf + (size_t)(bm + lrow) * NC_ + ((c) - 16) * 32;               \
    const float* pb = gB + (c) * 32;                                          \
    uint32_t abase = sb + (uint32_t)(stg) * 32768u + (uint32_t)lrow * 128u;   \
    _Pragma("unroll")                                                         \
    for (int j = 0; j < 4; j++) {                                             \
        uint32_t u = (uint32_t)(lu0 + j), ph = (u ^ swz) << 4;                \
        asm volatile("cp.async.cg.shared.global [%0], [%1], 16;"              \
                     :: "r"(abase + ph), "l"(pa + u * 4) : "memory");         \
        asm volatile("cp.async.cg.shared.global [%0], [%1], 16;"              \
                     :: "r"(abase + 16384u + ph), "l"(pb + u * 4) : "memory");\
    }                                                                         \
} while (0)

__global__ void __launch_bounds__(256) gemm_tf32_kernel(float* __restrict__ out,
                                                        int out_size)
{
    extern __shared__ __align__(1024) char sm[];   // 2 stages x (A 16KB + B 16KB)
    const int t = threadIdx.x, lane = t & 31, wid = t >> 5;
    const int wm = wid & 1, wn = wid >> 1;
    const int bm = blockIdx.y * 128, bn = blockIdx.x * 128;
    const uint32_t sb = smem_u32(sm);

    // fused KL scalar (g_klpart written by reduce_coeff, earlier in stream)
    if (blockIdx.x == 0 && blockIdx.y == 0 && t < 32) {
        float v = 0.f;
        for (int i = lane; i < OUT_; i += 32) v += g_klpart[i];
        #pragma unroll
        for (int off = 16; off > 0; off >>= 1) v += __shfl_down_sync(0xffffffffu, v, off);
        if (lane == 0) out[out_size - 1] = 0.5f * v;
    }

    // cp.async mapping: thread -> (row, 4 of 8 16B-units)
    const int lrow = t >> 1;
    const int lu0  = (t & 1) * 4;
    const uint32_t swz = (uint32_t)(lrow & 7);
    const float* gB = g_Bt + (size_t)(bn + lrow) * KA;

    // ldmatrix per-lane geometry (8x8 b16 matrix == 8 rows x 4 fp32)
    const int arow_off = (lane & 7) + 8 * ((lane >> 3) & 1);
    const int a_uo = lane >> 4;            // 0/1 : k cols 0-3 / 4-7
    const int brow_off = lane & 7;
    const int b_uo = (lane >> 3) & 1;

    float acc[4][4][4];
    #pragma unroll
    for (int mt = 0; mt < 4; mt++)
        #pragma unroll
        for (int nt = 0; nt < 4; nt++)
            #pragma unroll
            for (int r = 0; r < 4; r++) acc[mt][nt][r] = 0.f;

    LOADC(0, 0);
    asm volatile("cp.async.commit_group;" ::: "memory");
    LOADC(1, 1);
    asm volatile("cp.async.commit_group;" ::: "memory");

    #pragma unroll 1
    for (int c = 0; c < NCH; c++) {
        asm volatile("cp.async.wait_group 1;" ::: "memory");
        __syncthreads();
        const uint32_t st = sb + (uint32_t)(c & 1) * 32768u;

        #pragma unroll
        for (int ks = 0; ks < 4; ks++) {
            uint32_t a[4][4], b[4][2];
            #pragma unroll
            for (int mt = 0; mt < 4; mt++) {
                int row = wm * 64 + mt * 16 + arow_off;
                uint32_t u = (uint32_t)(ks * 2 + a_uo);
                uint32_t ad = st + (uint32_t)row * 128u +
                              ((u ^ (uint32_t)(row & 7)) << 4);
                asm volatile(
                    "ldmatrix.sync.aligned.m8n8.x4.shared.b16 {%0,%1,%2,%3}, [%4];"
                    : "=r"(a[mt][0]), "=r"(a[mt][1]), "=r"(a[mt][2]), "=r"(a[mt][3])
                    : "r"(ad));
            }
            #pragma unroll
            for (int nt = 0; nt < 4; nt++) {
                int row = wn * 32 + nt * 8 + brow_off;
                uint32_t u = (uint32_t)(ks * 2 + b_uo);
                uint32_t bd = st + 16384u + (uint32_t)row * 128u +
                              ((u ^ (uint32_t)(row & 7)) << 4);
                asm volatile(
                    "ldmatrix.sync.aligned.m8n8.x2.shared.b16 {%0,%1}, [%2];"
                    : "=r"(b[nt][0]), "=r"(b[nt][1])
                    : "r"(bd));
            }
            #pragma unroll
            for (int mt = 0; mt < 4; mt++)
                #pragma unroll
                for (int nt = 0; nt < 4; nt++)
                    asm volatile(
                        "mma.sync.aligned.m16n8k8.row.col.f32.tf32.tf32.f32 "
                        "{%0,%1,%2,%3}, {%4,%5,%6,%7}, {%8,%9}, {%0,%1,%2,%3};"
                        : "+f"(acc[mt][nt][0]), "+f"(acc[mt][nt][1]),
                          "+f"(acc[mt][nt][2]), "+f"(acc[mt][nt][3])
                        : "r"(a[mt][0]), "r"(a[mt][1]), "r"(a[mt][2]), "r"(a[mt][3]),
                          "r"(b[nt][0]), "r"(b[nt][1]));
        }

        __syncthreads();
        if (c + 2 < NCH) LOADC(c + 2, c & 1);
        asm volatile("cp.async.commit_group;" ::: "memory");
    }

    // epilogue
    const int er = lane >> 2, ec = (lane & 3) * 2;
    #pragma unroll
    for (int mt = 0; mt < 4; mt++) {
        int r0 = bm + wm * 64 + mt * 16 + er;
        #pragma unroll
        for (int nt = 0; nt < 4; nt++) {
            int col = bn + wn * 32 + nt * 8 + ec;
            *(float2*)&out[(size_t)r0 * OUT_ + col] =
                make_float2(acc[mt][nt][0], acc[mt][nt][1]);
            *(float2*)&out[(size_t)(r0 + 8) * OUT_ + col] =
                make_float2(acc[mt][nt][2], acc[mt][nt][3]);
        }
    }
}

// ---------------------------------------------------------------------------
extern "C" void kernel_launch(void* const* d_in, const int* in_sizes, int n_in,
                              void* d_out, int out_size)
{
    const float* x         = (const float*)d_in[0];
    const float* centers   = (const float*)d_in[1];
    const float* log_sigma = (const float*)d_in[2];
    const float* cm        = (const float*)d_in[3];
    const float* clv       = (const float*)d_in[4];
    const float* W         = (const float*)d_in[5];
    const float* ep        = (const float*)d_in[6];
    float* out = (float*)d_out;

    cudaFuncSetAttribute(gemm_tf32_kernel,
                         cudaFuncAttributeMaxDynamicSharedMemorySize, 65536);

    convert_w_kernel<<<dim3(16, 16), 256>>>(W);
    reduce_coeff_kernel<<<512, 256>>>(cm, clv, ep);
    rbf_fused_kernel<<<128, 256>>>(x, centers, log_sigma);
    gemm_tf32_kernel<<<dim3(OUT_ / 128, B_ / 128), 256, 65536>>>(out, out_size);
}

// round 13
// speedup vs baseline: 3.2981x; 1.0277x over previous
#include <cuda_runtime.h>
#include <math.h>
#include <stdint.h>

#define B_   4096
#define IN_  512
#define OUT_ 512
#define NC_  64
#define KA   576     // 512 (x|W) + 64 (rbf|c_sum)
#define NCH  18      // 576 / 32

// ---------------- scratch (__device__ globals; no allocation allowed) -------
__device__ __align__(16) float g_Ax[B_ * IN_];     // tf32-RN rounded x
__device__ __align__(16) float g_Arbf[B_ * NC_];   // tf32-RN rounded rbf
__device__ __align__(16) float g_Bt[OUT_ * KA];    // row o: [W^T | c_sumT], rounded
__device__ float g_klpart[OUT_];

__device__ __forceinline__ float rna_tf32(float v) {
    uint32_t u;
    asm("cvt.rna.tf32.f32 %0, %1;" : "=r"(u) : "f"(v));
    return __uint_as_float(u);
}
__device__ __forceinline__ uint32_t smem_u32(const void* p) {
    uint32_t a;
    asm("{ .reg .u64 t; cvta.to.shared.u64 t, %1; cvt.u32.u64 %0, t; }" : "=r"(a) : "l"(p));
    return a;
}

// ---------------------------------------------------------------------------
// convert_w: transpose W[k][o] -> g_Bt[o][k], tf32-RN rounded.
// ---------------------------------------------------------------------------
__global__ void __launch_bounds__(256) convert_w_kernel(const float* __restrict__ W)
{
    __shared__ float tile[32][33];
    int tx = threadIdx.x & 31, ty = threadIdx.x >> 5;
    int bx = blockIdx.x, by = blockIdx.y;

    #pragma unroll
    for (int i = 0; i < 4; i++)
        tile[ty + i * 8][tx] = W[(size_t)(by * 32 + ty + i * 8) * OUT_ + bx * 32 + tx];
    __syncthreads();

    #pragma unroll
    for (int i = 0; i < 4; i++) {
        int o = bx * 32 + ty + i * 8;
        int k = by * 32 + tx;
        g_Bt[(size_t)o * KA + k] = rna_tf32(tile[tx][ty + i * 8]);
    }
}

// ---------------------------------------------------------------------------
// reduce_coeff: c_sum[o][n] = sum_i (mean + eps*std) + KL partials per o.
// DRAM-bound (201 MB). Writes rounded c_sumT into g_Bt[o][512+n].
// ---------------------------------------------------------------------------
__global__ void __launch_bounds__(256) reduce_coeff_kernel(
    const float* __restrict__ cm, const float* __restrict__ clv,
    const float* __restrict__ ep)
{
    const int o = blockIdx.x, t = threadIdx.x;
    const int n4 = t & 15, isub = t >> 4;
    const float4* cm4  = (const float4*)cm;
    const float4* clv4 = (const float4*)clv;
    const float4* ep4  = (const float4*)ep;

    float4 ac = make_float4(0.f, 0.f, 0.f, 0.f);
    float akl = 0.f;
    #pragma unroll 4
    for (int i = isub; i < IN_; i += 16) {
        size_t idx = (size_t)i * 8192 + o * 16 + n4;   // float4 index
        float4 m  = __ldcs(cm4 + idx);
        float4 lv = __ldcs(clv4 + idx);
        float4 e  = __ldcs(ep4 + idx);
        float s0 = __expf(0.5f * lv.x), s1 = __expf(0.5f * lv.y);
        float s2 = __expf(0.5f * lv.z), s3 = __expf(0.5f * lv.w);
        ac.x += m.x + e.x * s0;  ac.y += m.y + e.y * s1;
        ac.z += m.z + e.z * s2;  ac.w += m.w + e.w * s3;
        akl += (s0*s0 + m.x*m.x - 1.f - lv.x) + (s1*s1 + m.y*m.y - 1.f - lv.y)
             + (s2*s2 + m.z*m.z - 1.f - lv.z) + (s3*s3 + m.w*m.w - 1.f - lv.w);
    }

    __shared__ float4 sc[16][16];   // [isub][n4]
    __shared__ float  sk[256];
    sc[isub][n4] = ac;
    sk[t] = akl;
    __syncthreads();

    if (t < 64) {
        float sum = 0.f;
        #pragma unroll
        for (int s2i = 0; s2i < 16; s2i++)
            sum += ((const float*)&sc[s2i][0])[t];
        g_Bt[(size_t)o * KA + 512 + t] = rna_tf32(sum);
    }
    if (t < 128) sk[t] += sk[t + 128];
    __syncthreads();
    if (t < 64) sk[t] += sk[t + 64];
    __syncthreads();
    if (t < 32) {
        float v = sk[t] + sk[t + 32];
        #pragma unroll
        for (int off = 16; off > 0; off >>= 1) v += __shfl_down_sync(0xffffffffu, v, off);
        if (t == 0) g_klpart[o] = v;
    }
}

// ---------------------------------------------------------------------------
// rbf_fused: dot = x.c SIMT GEMM + |c|^2 + sigma + tf32 passthrough of x.
// ---------------------------------------------------------------------------
__global__ void __launch_bounds__(256) rbf_fused_kernel(
    const float* __restrict__ x, const float* __restrict__ centers,
    const float* __restrict__ log_sigma)
{
    __shared__ float As[32][33];   // [k][row]
    __shared__ float Cs[32][68];   // [k][n]
    const int t = threadIdx.x;
    const int bm = blockIdx.x * 32;
    const int tx = t & 15, ty = t >> 4;

    float acc[2][4] = {{0.f,0.f,0.f,0.f},{0.f,0.f,0.f,0.f}};
    float sq0 = 0.f, sq1 = 0.f;
    float c2[4] = {0.f, 0.f, 0.f, 0.f};

    for (int kt = 0; kt < 16; kt++) {
        {   int row = t >> 3, kq = (t & 7) * 4;
            float4 v = *(const float4*)&x[(size_t)(bm + row) * IN_ + kt * 32 + kq];
            As[kq][row] = v.x; As[kq+1][row] = v.y; As[kq+2][row] = v.z; As[kq+3][row] = v.w;
            float4 rv = make_float4(rna_tf32(v.x), rna_tf32(v.y),
                                    rna_tf32(v.z), rna_tf32(v.w));
            *(float4*)&g_Ax[(size_t)(bm + row) * IN_ + kt * 32 + kq] = rv;
        }
        {   int n = t >> 2, kq = (t & 3) * 8;
            const float* src = &centers[(size_t)n * IN_ + kt * 32 + kq];
            float4 v0 = *(const float4*)src;
            float4 v1 = *(const float4*)(src + 4);
            Cs[kq  ][n] = v0.x; Cs[kq+1][n] = v0.y; Cs[kq+2][n] = v0.z; Cs[kq+3][n] = v0.w;
            Cs[kq+4][n] = v1.x; Cs[kq+5][n] = v1.y; Cs[kq+6][n] = v1.z; Cs[kq+7][n] = v1.w;
        }
        __syncthreads();
        #pragma unroll
        for (int k = 0; k < 32; k++) {
            float a0 = As[k][ty * 2], a1 = As[k][ty * 2 + 1];
            float4 c = *(const float4*)&Cs[k][tx * 4];
            acc[0][0] += a0 * c.x; acc[0][1] += a0 * c.y;
            acc[0][2] += a0 * c.z; acc[0][3] += a0 * c.w;
            acc[1][0] += a1 * c.x; acc[1][1] += a1 * c.y;
            acc[1][2] += a1 * c.z; acc[1][3] += a1 * c.w;
            sq0 += a0 * a0; sq1 += a1 * a1;
            c2[0] += c.x * c.x; c2[1] += c.y * c.y;
            c2[2] += c.z * c.z; c2[3] += c.w * c.w;
        }
        __syncthreads();
    }

    float inv[4];
    #pragma unroll
    for (int j = 0; j < 4; j++) {
        float sg = __expf(log_sigma[tx * 4 + j]);
        inv[j] = 1.0f / (2.0f * sg * sg + 1e-8f);
    }
    #pragma unroll
    for (int i = 0; i < 2; i++) {
        float sq = i ? sq1 : sq0;
        size_t base = (size_t)(bm + ty * 2 + i) * NC_;
        #pragma unroll
        for (int j = 0; j < 4; j++) {
            float d2 = sq - 2.f * acc[i][j] + c2[j];
            g_Arbf[base + tx * 4 + j] = rna_tf32(__expf(-d2 * inv[j]));
        }
    }
}

// ---------------------------------------------------------------------------
// tf32 mma GEMM: out[4096x512] = [g_Ax | g_Arbf] @ g_Bt^T, K = 576.
// 128x128x32 CTA tile, 8 warps (2x4), warp tile 64x32, XOR-swizzled fp32 smem,
// ldmatrix-b16 fragment loads. THREE-stage cp.async pipeline: loads for chunk
// c+2 issue right after wait(chunk c), BEFORE the MMA on chunk c, so memory
// latency hides behind a full chunk of tensor work. Fused KL in block (0,0).
// ---------------------------------------------------------------------------
#define LOADC(c, stg) do {                                                    \
    const float* pa = ((c) < 16)                                              \
        ? g_Ax + (size_t)(bm + lrow) * IN_ + (c) * 32                         \
        : g_Arbf + (size_t)(bm + lrow) * NC_ + ((c) - 16) * 32;               \
    const float* pb = gB + (c) * 32;                                          \
    uint32_t abase = sb + (uint32_t)(stg) * 32768u + (uint32_t)lrow * 128u;   \
    _Pragma("unroll")                                                         \
    for (int j = 0; j < 4; j++) {                                             \
        uint32_t u = (uint32_t)(lu0 + j), ph = (u ^ swz) << 4;                \
        asm volatile("cp.async.cg.shared.global [%0], [%1], 16;"              \
                     :: "r"(abase + ph), "l"(pa + u * 4) : "memory");         \
        asm volatile("cp.async.cg.shared.global [%0], [%1], 16;"              \
                     :: "r"(abase + 16384u + ph), "l"(pb + u * 4) : "memory");\
    }                                                                         \
} while (0)

__global__ void __launch_bounds__(256) gemm_tf32_kernel(float* __restrict__ out,
                                                        int out_size)
{
    extern __shared__ __align__(1024) char sm[];   // 3 stages x (A 16KB + B 16KB)
    const int t = threadIdx.x, lane = t & 31, wid = t >> 5;
    const int wm = wid & 1, wn = wid >> 1;
    const int bm = blockIdx.y * 128, bn = blockIdx.x * 128;
    const uint32_t sb = smem_u32(sm);

    // fused KL scalar (g_klpart written by reduce_coeff, earlier in stream)
    if (blockIdx.x == 0 && blockIdx.y == 0 && t < 32) {
        float v = 0.f;
        for (int i = lane; i < OUT_; i += 32) v += g_klpart[i];
        #pragma unroll
        for (int off = 16; off > 0; off >>= 1) v += __shfl_down_sync(0xffffffffu, v, off);
        if (lane == 0) out[out_size - 1] = 0.5f * v;
    }

    // cp.async mapping: thread -> (row, 4 of 8 16B-units)
    const int lrow = t >> 1;
    const int lu0  = (t & 1) * 4;
    const uint32_t swz = (uint32_t)(lrow & 7);
    const float* gB = g_Bt + (size_t)(bn + lrow) * KA;

    // ldmatrix per-lane geometry (8x8 b16 matrix == 8 rows x 4 fp32)
    const int arow_off = (lane & 7) + 8 * ((lane >> 3) & 1);
    const int a_uo = lane >> 4;            // 0/1 : k cols 0-3 / 4-7
    const int brow_off = lane & 7;
    const int b_uo = (lane >> 3) & 1;

    float acc[4][4][4];
    #pragma unroll
    for (int mt = 0; mt < 4; mt++)
        #pragma unroll
        for (int nt = 0; nt < 4; nt++)
            #pragma unroll
            for (int r = 0; r < 4; r++) acc[mt][nt][r] = 0.f;

    LOADC(0, 0);
    asm volatile("cp.async.commit_group;" ::: "memory");
    LOADC(1, 1);
    asm volatile("cp.async.commit_group;" ::: "memory");

    #pragma unroll 1
    for (int c = 0; c < NCH; c++) {
        asm volatile("cp.async.wait_group 1;" ::: "memory");
        __syncthreads();
        // prefetch chunk c+2 into stage (c+2)%3 (== (c-1)%3, drained at c-1)
        if (c + 2 < NCH) LOADC(c + 2, (c + 2) % 3);
        asm volatile("cp.async.commit_group;" ::: "memory");

        const uint32_t st = sb + (uint32_t)(c % 3) * 32768u;
        #pragma unroll
        for (int ks = 0; ks < 4; ks++) {
            uint32_t a[4][4], b[4][2];
            #pragma unroll
            for (int mt = 0; mt < 4; mt++) {
                int row = wm * 64 + mt * 16 + arow_off;
                uint32_t u = (uint32_t)(ks * 2 + a_uo);
                uint32_t ad = st + (uint32_t)row * 128u +
                              ((u ^ (uint32_t)(row & 7)) << 4);
                asm volatile(
                    "ldmatrix.sync.aligned.m8n8.x4.shared.b16 {%0,%1,%2,%3}, [%4];"
                    : "=r"(a[mt][0]), "=r"(a[mt][1]), "=r"(a[mt][2]), "=r"(a[mt][3])
                    : "r"(ad));
            }
            #pragma unroll
            for (int nt = 0; nt < 4; nt++) {
                int row = wn * 32 + nt * 8 + brow_off;
                uint32_t u = (uint32_t)(ks * 2 + b_uo);
                uint32_t bd = st + 16384u + (uint32_t)row * 128u +
                              ((u ^ (uint32_t)(row & 7)) << 4);
                asm volatile(
                    "ldmatrix.sync.aligned.m8n8.x2.shared.b16 {%0,%1}, [%2];"
                    : "=r"(b[nt][0]), "=r"(b[nt][1])
                    : "r"(bd));
            }
            #pragma unroll
            for (int mt = 0; mt < 4; mt++)
                #pragma unroll
                for (int nt = 0; nt < 4; nt++)
                    asm volatile(
                        "mma.sync.aligned.m16n8k8.row.col.f32.tf32.tf32.f32 "
                        "{%0,%1,%2,%3}, {%4,%5,%6,%7}, {%8,%9}, {%0,%1,%2,%3};"
                        : "+f"(acc[mt][nt][0]), "+f"(acc[mt][nt][1]),
                          "+f"(acc[mt][nt][2]), "+f"(acc[mt][nt][3])
                        : "r"(a[mt][0]), "r"(a[mt][1]), "r"(a[mt][2]), "r"(a[mt][3]),
                          "r"(b[nt][0]), "r"(b[nt][1]));
        }
    }

    // epilogue
    const int er = lane >> 2, ec = (lane & 3) * 2;
    #pragma unroll
    for (int mt = 0; mt < 4; mt++) {
        int r0 = bm + wm * 64 + mt * 16 + er;
        #pragma unroll
        for (int nt = 0; nt < 4; nt++) {
            int col = bn + wn * 32 + nt * 8 + ec;
            *(float2*)&out[(size_t)r0 * OUT_ + col] =
                make_float2(acc[mt][nt][0], acc[mt][nt][1]);
            *(float2*)&out[(size_t)(r0 + 8) * OUT_ + col] =
                make_float2(acc[mt][nt][2], acc[mt][nt][3]);
        }
    }
}

// ---------------------------------------------------------------------------
extern "C" void kernel_launch(void* const* d_in, const int* in_sizes, int n_in,
                              void* d_out, int out_size)
{
    const float* x         = (const float*)d_in[0];
    const float* centers   = (const float*)d_in[1];
    const float* log_sigma = (const float*)d_in[2];
    const float* cm        = (const float*)d_in[3];
    const float* clv       = (const float*)d_in[4];
    const float* W         = (const float*)d_in[5];
    const float* ep        = (const float*)d_in[6];
    float* out = (float*)d_out;

    cudaFuncSetAttribute(gemm_tf32_kernel,
                         cudaFuncAttributeMaxDynamicSharedMemorySize, 98304);

    convert_w_kernel<<<dim3(16, 16), 256>>>(W);
    reduce_coeff_kernel<<<512, 256>>>(cm, clv, ep);
    rbf_fused_kernel<<<128, 256>>>(x, centers, log_sigma);
    gemm_tf32_kernel<<<dim3(OUT_ / 128, B_ / 128), 256, 98304>>>(out, out_size);
}

// round 16
// speedup vs baseline: 3.4270x; 1.0391x over previous
#include <cuda_runtime.h>
#include <math.h>
#include <stdint.h>

#define B_   4096
#define IN_  512
#define OUT_ 512
#define NC_  64
#define KA   576     // 512 (x|W) + 64 (rbf|c_sum)
#define NCH  18      // 576 / 32

#define STG_BYTES 24576u   // per stage: A 8KB + B 16KB
#define B_OFF     8192u    // B area offset within a stage

// ---------------- scratch (__device__ globals; no allocation allowed) -------
__device__ __align__(16) float g_Ax[B_ * IN_];     // tf32-RN rounded x
__device__ __align__(16) float g_Arbf[B_ * NC_];   // tf32-RN rounded rbf
__device__ __align__(16) float g_Bt[OUT_ * KA];    // row o: [W^T | c_sumT], rounded
__device__ float g_klpart[OUT_];

__device__ __forceinline__ float rna_tf32(float v) {
    uint32_t u;
    asm("cvt.rna.tf32.f32 %0, %1;" : "=r"(u) : "f"(v));
    return __uint_as_float(u);
}
__device__ __forceinline__ uint32_t smem_u32(const void* p) {
    uint32_t a;
    asm("{ .reg .u64 t; cvta.to.shared.u64 t, %1; cvt.u32.u64 %0, t; }" : "=r"(a) : "l"(p));
    return a;
}

// ---------------------------------------------------------------------------
// convert_w: transpose W[k][o] -> g_Bt[o][k], tf32-RN rounded.
// ---------------------------------------------------------------------------
__global__ void __launch_bounds__(256) convert_w_kernel(const float* __restrict__ W)
{
    __shared__ float tile[32][33];
    int tx = threadIdx.x & 31, ty = threadIdx.x >> 5;
    int bx = blockIdx.x, by = blockIdx.y;

    #pragma unroll
    for (int i = 0; i < 4; i++)
        tile[ty + i * 8][tx] = W[(size_t)(by * 32 + ty + i * 8) * OUT_ + bx * 32 + tx];
    __syncthreads();

    #pragma unroll
    for (int i = 0; i < 4; i++) {
        int o = bx * 32 + ty + i * 8;
        int k = by * 32 + tx;
        g_Bt[(size_t)o * KA + k] = rna_tf32(tile[tx][ty + i * 8]);
    }
}

// ---------------------------------------------------------------------------
// reduce_coeff: c_sum[o][n] = sum_i (mean + eps*std) + KL partials per o.
// DRAM-bound (201 MB). Writes rounded c_sumT into g_Bt[o][512+n].
// ---------------------------------------------------------------------------
__global__ void __launch_bounds__(256) reduce_coeff_kernel(
    const float* __restrict__ cm, const float* __restrict__ clv,
    const float* __restrict__ ep)
{
    const int o = blockIdx.x, t = threadIdx.x;
    const int n4 = t & 15, isub = t >> 4;
    const float4* cm4  = (const float4*)cm;
    const float4* clv4 = (const float4*)clv;
    const float4* ep4  = (const float4*)ep;

    float4 ac = make_float4(0.f, 0.f, 0.f, 0.f);
    float akl = 0.f;
    #pragma unroll 4
    for (int i = isub; i < IN_; i += 16) {
        size_t idx = (size_t)i * 8192 + o * 16 + n4;   // float4 index
        float4 m  = __ldcs(cm4 + idx);
        float4 lv = __ldcs(clv4 + idx);
        float4 e  = __ldcs(ep4 + idx);
        float s0 = __expf(0.5f * lv.x), s1 = __expf(0.5f * lv.y);
        float s2 = __expf(0.5f * lv.z), s3 = __expf(0.5f * lv.w);
        ac.x += m.x + e.x * s0;  ac.y += m.y + e.y * s1;
        ac.z += m.z + e.z * s2;  ac.w += m.w + e.w * s3;
        akl += (s0*s0 + m.x*m.x - 1.f - lv.x) + (s1*s1 + m.y*m.y - 1.f - lv.y)
             + (s2*s2 + m.z*m.z - 1.f - lv.z) + (s3*s3 + m.w*m.w - 1.f - lv.w);
    }

    __shared__ float4 sc[16][16];   // [isub][n4]
    __shared__ float  sk[256];
    sc[isub][n4] = ac;
    sk[t] = akl;
    __syncthreads();

    if (t < 64) {
        float sum = 0.f;
        #pragma unroll
        for (int s2i = 0; s2i < 16; s2i++)
            sum += ((const float*)&sc[s2i][0])[t];
        g_Bt[(size_t)o * KA + 512 + t] = rna_tf32(sum);
    }
    if (t < 128) sk[t] += sk[t + 128];
    __syncthreads();
    if (t < 64) sk[t] += sk[t + 64];
    __syncthreads();
    if (t < 32) {
        float v = sk[t] + sk[t + 32];
        #pragma unroll
        for (int off = 16; off > 0; off >>= 1) v += __shfl_down_sync(0xffffffffu, v, off);
        if (t == 0) g_klpart[o] = v;
    }
}

// ---------------------------------------------------------------------------
// rbf_fused: dot = x.c SIMT GEMM + |c|^2 + sigma + tf32 passthrough of x.
// ---------------------------------------------------------------------------
__global__ void __launch_bounds__(256) rbf_fused_kernel(
    const float* __restrict__ x, const float* __restrict__ centers,
    const float* __restrict__ log_sigma)
{
    __shared__ float As[32][33];   // [k][row]
    __shared__ float Cs[32][68];   // [k][n]
    const int t = threadIdx.x;
    const int bm = blockIdx.x * 32;
    const int tx = t & 15, ty = t >> 4;

    float acc[2][4] = {{0.f,0.f,0.f,0.f},{0.f,0.f,0.f,0.f}};
    float sq0 = 0.f, sq1 = 0.f;
    float c2[4] = {0.f, 0.f, 0.f, 0.f};

    for (int kt = 0; kt < 16; kt++) {
        {   int row = t >> 3, kq = (t & 7) * 4;
            float4 v = *(const float4*)&x[(size_t)(bm + row) * IN_ + kt * 32 + kq];
            As[kq][row] = v.x; As[kq+1][row] = v.y; As[kq+2][row] = v.z; As[kq+3][row] = v.w;
            float4 rv = make_float4(rna_tf32(v.x), rna_tf32(v.y),
                                    rna_tf32(v.z), rna_tf32(v.w));
            *(float4*)&g_Ax[(size_t)(bm + row) * IN_ + kt * 32 + kq] = rv;
        }
        {   int n = t >> 2, kq = (t & 3) * 8;
            const float* src = &centers[(size_t)n * IN_ + kt * 32 + kq];
            float4 v0 = *(const float4*)src;
            float4 v1 = *(const float4*)(src + 4);
            Cs[kq  ][n] = v0.x; Cs[kq+1][n] = v0.y; Cs[kq+2][n] = v0.z; Cs[kq+3][n] = v0.w;
            Cs[kq+4][n] = v1.x; Cs[kq+5][n] = v1.y; Cs[kq+6][n] = v1.z; Cs[kq+7][n] = v1.w;
        }
        __syncthreads();
        #pragma unroll
        for (int k = 0; k < 32; k++) {
            float a0 = As[k][ty * 2], a1 = As[k][ty * 2 + 1];
            float4 c = *(const float4*)&Cs[k][tx * 4];
            acc[0][0] += a0 * c.x; acc[0][1] += a0 * c.y;
            acc[0][2] += a0 * c.z; acc[0][3] += a0 * c.w;
            acc[1][0] += a1 * c.x; acc[1][1] += a1 * c.y;
            acc[1][2] += a1 * c.z; acc[1][3] += a1 * c.w;
            sq0 += a0 * a0; sq1 += a1 * a1;
            c2[0] += c.x * c.x; c2[1] += c.y * c.y;
            c2[2] += c.z * c.z; c2[3] += c.w * c.w;
        }
        __syncthreads();
    }

    float inv[4];
    #pragma unroll
    for (int j = 0; j < 4; j++) {
        float sg = __expf(log_sigma[tx * 4 + j]);
        inv[j] = 1.0f / (2.0f * sg * sg + 1e-8f);
    }
    #pragma unroll
    for (int i = 0; i < 2; i++) {
        float sq = i ? sq1 : sq0;
        size_t base = (size_t)(bm + ty * 2 + i) * NC_;
        #pragma unroll
        for (int j = 0; j < 4; j++) {
            float d2 = sq - 2.f * acc[i][j] + c2[j];
            g_Arbf[base + tx * 4 + j] = rna_tf32(__expf(-d2 * inv[j]));
        }
    }
}

// ---------------------------------------------------------------------------
// tf32 mma GEMM: out[4096x512] = [g_Ax | g_Arbf] @ g_Bt^T, K = 576.
// 64x128 CTA tile (grid 4x64 = 256 CTAs, 3 CTAs/SM -> 24 warps/SM for latency
// hiding). 8 warps as 2(M)x4(N), warp tile 32x32. 3-stage cp.async pipeline,
// XOR-swizzled fp32 smem, ldmatrix-b16 fragments. Fused KL in block (0,0).
// ---------------------------------------------------------------------------
#define LOADC(c, stg) do {                                                    \
    uint32_t base_ = sb + (uint32_t)(stg) * STG_BYTES;                        \
    if (t < 128) {  /* A: 64 rows x 32 floats */                              \
        const float* pa = ((c) < 16)                                          \
            ? g_Ax + (size_t)(bm + lrow) * IN_ + (c) * 32                     \
            : g_Arbf + (size_t)(bm + lrow) * NC_ + ((c) - 16) * 32;           \
        uint32_t ab = base_ + (uint32_t)lrow * 128u;                          \
        _Pragma("unroll")                                                     \
        for (int j = 0; j < 4; j++) {                                         \
            uint32_t u = (uint32_t)(lu0 + j), ph = (u ^ swz) << 4;            \
            asm volatile("cp.async.cg.shared.global [%0], [%1], 16;"          \
                         :: "r"(ab + ph), "l"(pa + u * 4) : "memory");        \
        }                                                                     \
    }                                                                         \
    {   /* B: 128 rows x 32 floats */                                         \
        const float* pb = gB + (c) * 32;                                      \
        uint32_t bb = base_ + B_OFF + (uint32_t)lrow * 128u;                  \
        _Pragma("unroll")                                                     \
        for (int j = 0; j < 4; j++) {                                         \
            uint32_t u = (uint32_t)(lu0 + j), ph = (u ^ swz) << 4;            \
            asm volatile("cp.async.cg.shared.global [%0], [%1], 16;"          \
                         :: "r"(bb + ph), "l"(pb + u * 4) : "memory");        \
        }                                                                     \
    }                                                                         \
} while (0)

__global__ void __launch_bounds__(256, 3) gemm_tf32_kernel(float* __restrict__ out,
                                                           int out_size)
{
    extern __shared__ __align__(1024) char sm[];   // 3 stages x 24KB
    const int t = threadIdx.x, lane = t & 31, wid = t >> 5;
    const int wm = wid & 1, wn = wid >> 1;         // 2(M) x 4(N)
    const int bm = blockIdx.y * 64, bn = blockIdx.x * 128;
    const uint32_t sb = smem_u32(sm);

    // fused KL scalar (g_klpart written by reduce_coeff, earlier in stream)
    if (blockIdx.x == 0 && blockIdx.y == 0 && t < 32) {
        float v = 0.f;
        for (int i = lane; i < OUT_; i += 32) v += g_klpart[i];
        #pragma unroll
        for (int off = 16; off > 0; off >>= 1) v += __shfl_down_sync(0xffffffffu, v, off);
        if (lane == 0) out[out_size - 1] = 0.5f * v;
    }

    // cp.async mapping
    const int lrow = t >> 1;                       // A rows: t<128 -> 0..63
    const int lu0  = (t & 1) * 4;
    const uint32_t swz = (uint32_t)(lrow & 7);
    const float* gB = g_Bt + (size_t)(bn + lrow) * KA;

    // ldmatrix per-lane geometry (8x8 b16 matrix == 8 rows x 4 fp32)
    const int arow_off = (lane & 7) + 8 * ((lane >> 3) & 1);
    const int a_uo = lane >> 4;            // 0/1 : k cols 0-3 / 4-7
    const int brow_off = lane & 7;
    const int b_uo = (lane >> 3) & 1;

    float acc[2][4][4];
    #pragma unroll
    for (int mt = 0; mt < 2; mt++)
        #pragma unroll
        for (int nt = 0; nt < 4; nt++)
            #pragma unroll
            for (int r = 0; r < 4; r++) acc[mt][nt][r] = 0.f;

    LOADC(0, 0);
    asm volatile("cp.async.commit_group;" ::: "memory");
    LOADC(1, 1);
    asm volatile("cp.async.commit_group;" ::: "memory");

    #pragma unroll 1
    for (int c = 0; c < NCH; c++) {
        asm volatile("cp.async.wait_group 1;" ::: "memory");
        __syncthreads();
        // prefetch chunk c+2 into stage (c+2)%3 (drained at iter c-1)
        if (c + 2 < NCH) LOADC(c + 2, (c + 2) % 3);
        asm volatile("cp.async.commit_group;" ::: "memory");

        const uint32_t st = sb + (uint32_t)(c % 3) * STG_BYTES;
        #pragma unroll
        for (int ks = 0; ks < 4; ks++) {
            uint32_t a[2][4], b[4][2];
            #pragma unroll
            for (int mt = 0; mt < 2; mt++) {
                int row = wm * 32 + mt * 16 + arow_off;
                uint32_t u = (uint32_t)(ks * 2 + a_uo);
                uint32_t ad = st + (uint32_t)row * 128u +
                              ((u ^ (uint32_t)(row & 7)) << 4);
                asm volatile(
                    "ldmatrix.sync.aligned.m8n8.x4.shared.b16 {%0,%1,%2,%3}, [%4];"
                    : "=r"(a[mt][0]), "=r"(a[mt][1]), "=r"(a[mt][2]), "=r"(a[mt][3])
                    : "r"(ad));
            }
            #pragma unroll
            for (int nt = 0; nt < 4; nt++) {
                int row = wn * 32 + nt * 8 + brow_off;
                uint32_t u = (uint32_t)(ks * 2 + b_uo);
                uint32_t bd = st + B_OFF + (uint32_t)row * 128u +
                              ((u ^ (uint32_t)(row & 7)) << 4);
                asm volatile(
                    "ldmatrix.sync.aligned.m8n8.x2.shared.b16 {%0,%1}, [%2];"
                    : "=r"(b[nt][0]), "=r"(b[nt][1])
                    : "r"(bd));
            }
            #pragma unroll
            for (int mt = 0; mt < 2; mt++)
                #pragma unroll
                for (int nt = 0; nt < 4; nt++)
                    asm volatile(
                        "mma.sync.aligned.m16n8k8.row.col.f32.tf32.tf32.f32 "
                        "{%0,%1,%2,%3}, {%4,%5,%6,%7}, {%8,%9}, {%0,%1,%2,%3};"
                        : "+f"(acc[mt][nt][0]), "+f"(acc[mt][nt][1]),
                          "+f"(acc[mt][nt][2]), "+f"(acc[mt][nt][3])
                        : "r"(a[mt][0]), "r"(a[mt][1]), "r"(a[mt][2]), "r"(a[mt][3]),
                          "r"(b[nt][0]), "r"(b[nt][1]));
        }
    }

    // epilogue
    const int er = lane >> 2, ec = (lane & 3) * 2;
    #pragma unroll
    for (int mt = 0; mt < 2; mt++) {
        int r0 = bm + wm * 32 + mt * 16 + er;
        #pragma unroll
        for (int nt = 0; nt < 4; nt++) {
            int col = bn + wn * 32 + nt * 8 + ec;
            *(float2*)&out[(size_t)r0 * OUT_ + col] =
                make_float2(acc[mt][nt][0], acc[mt][nt][1]);
            *(float2*)&out[(size_t)(r0 + 8) * OUT_ + col] =
                make_float2(acc[mt][nt][2], acc[mt][nt][3]);
        }
    }
}

// ---------------------------------------------------------------------------
extern "C" void kernel_launch(void* const* d_in, const int* in_sizes, int n_in,
                              void* d_out, int out_size)
{
    const float* x         = (const float*)d_in[0];
    const float* centers   = (const float*)d_in[1];
    const float* log_sigma = (const float*)d_in[2];
    const float* cm        = (const float*)d_in[3];
    const float* clv       = (const float*)d_in[4];
    const float* W         = (const float*)d_in[5];
    const float* ep        = (const float*)d_in[6];
    float* out = (float*)d_out;

    cudaFuncSetAttribute(gemm_tf32_kernel,
                         cudaFuncAttributeMaxDynamicSharedMemorySize, 3 * STG_BYTES);

    convert_w_kernel<<<dim3(16, 16), 256>>>(W);
    reduce_coeff_kernel<<<512, 256>>>(cm, clv, ep);
    rbf_fused_kernel<<<128, 256>>>(x, centers, log_sigma);
    gemm_tf32_kernel<<<dim3(OUT_ / 128, B_ / 64), 256, 3 * STG_BYTES>>>(out, out_size);
}